// round 3
// baseline (speedup 1.0000x reference)
#include <cuda_runtime.h>
#include <math.h>

// Problem constants
#define NCHUNK 32
#define NBATCH 64
#define HALF   128
#define SIZE   (2 * HALF)            // 256
#define NROWS  (NCHUNK * NBATCH)     // 2048
#define C_SCALE 1e-4f
#define M_SCALE 1e-5f

#define YDOT_FLOATS (NROWS * SIZE)   // 524288

// Persistent exact-fit grid: 8 blocks/SM x 148 SMs = 1184 blocks.
// J broadcast mapping: 32 segments x 37 groups = 1184.
//   Each block owns one 8KB segment (512 float4) of the 256KB Jb block,
//   held as 2 float4 per thread in registers, and strides over the 2048
//   batch copies with step 37 (55-56 copies per block, ~2% imbalance).
#define NBLK 1184
#define SEGS 32
#define GRPS 37
#define SEG_F4 512                   // float4 per segment

// ---------------------------------------------------------------------------
// Closed-form Jb[r][c] (256x256)
// ---------------------------------------------------------------------------
__device__ __forceinline__ float jb_val(int r, int c,
                                        const float* __restrict__ K,
                                        const float* __restrict__ C,
                                        const float* __restrict__ M) {
    if (r < HALF) {
        return (c == r + HALF) ? 1.0f : 0.0f;
    }
    int i = r - HALF;
    int j = (c < HALF) ? c : (c - HALF);
    int d = j - i;
    if (d < -1 || d > 1) return 0.0f;

    float Mi = M[i] * M_SCALE;
    if (c < HALF) {
        if (d == 0) {
            float v = -K[i] / Mi;
            if (i > 0) v -= K[i - 1] / Mi;
            return v;
        } else if (d == 1) {
            return K[i] / Mi;
        } else {
            return K[i - 1] / Mi;
        }
    } else {
        if (d == 0) {
            float v = -(C[i] * C_SCALE) / Mi;
            if (i > 0) v -= (C[i - 1] * C_SCALE) / Mi;
            return v;
        } else if (d == 1) {
            return (C[i] * C_SCALE) / Mi;
        } else {
            return (C[i - 1] * C_SCALE) / Mi;
        }
    }
}

// ---------------------------------------------------------------------------
// ONE fused persistent kernel: 1184 blocks x 256 threads, 8 blocks/SM.
// ---------------------------------------------------------------------------
__global__ void __launch_bounds__(SIZE, 8)
fused_kernel(const float* __restrict__ t,
             const float* __restrict__ y,
             const float* __restrict__ K,
             const float* __restrict__ C,
             const float* __restrict__ M,
             float* __restrict__ out) {
    __shared__ float sm[SIZE];   // [u(128) | v(128)]
    int bid = blockIdx.x;
    int tid = threadIdx.x;

    // ---- Part A: ydot rows, strided over the persistent grid --------------
    for (int row = bid; row < NROWS; row += NBLK) {
        sm[tid] = y[row * SIZE + tid];
        __syncthreads();

        float res;
        if (tid < HALF) {
            res = sm[HALF + tid];                 // ydot[:half] = v
        } else {
            int i = tid - HALF;
            float Mi = M[i] * M_SCALE;
            float acc = 0.0f;
            if (i < HALF - 1) {
                float f = K[i] * (sm[i + 1] - sm[i])
                        + (C[i] * C_SCALE) * (sm[HALF + i + 1] - sm[HALF + i]);
                acc += f / Mi;
            }
            if (i > 0) {
                float fm = K[i - 1] * (sm[i] - sm[i - 1])
                         + (C[i - 1] * C_SCALE) * (sm[HALF + i] - sm[HALF + i - 1]);
                acc -= fm / Mi;
            }
            if (i == HALF - 1) {
                acc -= (K[HALF - 1] * sm[HALF - 1]
                      + (C[HALF - 1] * C_SCALE) * sm[SIZE - 1]) / Mi;
            }
            if (i == 0) {
                acc += sinf(t[row]) / Mi;
            }
            res = acc;
        }
        out[row * SIZE + tid] = res;
        __syncthreads();   // protect sm before next iteration's load
    }

    // ---- Part B: compute this thread's 2 float4 of its Jb segment ---------
    int s = bid & (SEGS - 1);        // segment 0..31
    int g = bid >> 5;                // group   0..36
    int segBase = s * SEG_F4;        // float4 index within one Jb copy

    float4 jr0, jr1;
    {
        int e0 = (segBase + tid) * 4;          // linear float index in Jb
        int r0 = e0 >> 8, c0 = e0 & (SIZE - 1);
        jr0.x = jb_val(r0, c0 + 0, K, C, M);
        jr0.y = jb_val(r0, c0 + 1, K, C, M);
        jr0.z = jb_val(r0, c0 + 2, K, C, M);
        jr0.w = jb_val(r0, c0 + 3, K, C, M);

        int e1 = (segBase + 256 + tid) * 4;
        int r1 = e1 >> 8, c1 = e1 & (SIZE - 1);
        jr1.x = jb_val(r1, c1 + 0, K, C, M);
        jr1.y = jb_val(r1, c1 + 1, K, C, M);
        jr1.z = jb_val(r1, c1 + 2, K, C, M);
        jr1.w = jb_val(r1, c1 + 3, K, C, M);
    }

    // ---- Part B: broadcast J (register replay, coalesced STG.128) ---------
    float4* __restrict__ j4 = reinterpret_cast<float4*>(out + YDOT_FLOATS);
    #pragma unroll 4
    for (int k = g; k < NROWS; k += GRPS) {
        float4* dst = j4 + (long long)k * 16384 + segBase + tid;
        dst[0]   = jr0;
        dst[256] = jr1;
    }
}

// ---------------------------------------------------------------------------
extern "C" void kernel_launch(void* const* d_in, const int* in_sizes, int n_in,
                              void* d_out, int out_size) {
    const float* t = (const float*)d_in[0];
    const float* y = (const float*)d_in[1];
    const float* K = (const float*)d_in[2];
    const float* C = (const float*)d_in[3];
    const float* M = (const float*)d_in[4];
    float* out = (float*)d_out;

    fused_kernel<<<NBLK, SIZE>>>(t, y, K, C, M, out);
}

// round 4
// speedup vs baseline: 1.0184x; 1.0184x over previous
#include <cuda_runtime.h>
#include <math.h>

// Problem constants
#define NCHUNK 32
#define NBATCH 64
#define HALF   128
#define SIZE   (2 * HALF)            // 256
#define NROWS  (NCHUNK * NBATCH)     // 2048
#define C_SCALE 1e-4f
#define M_SCALE 1e-5f

#define YDOT_FLOATS (NROWS * SIZE)   // 524288

// J broadcast mapping: 16 segments x 111 groups = 1776 blocks
//   = EXACTLY 2.0 waves at 6 blocks/SM (regs ~42) x 148 SMs.
// Each block owns one 16KB segment (1024 float4) of the 256KB Jb block,
// held as 4 float4 per thread in registers, and strides over the 2048
// batch copies with step 111 (18-19 copies per block).
#define SEGS 16
#define GRPS 111
#define NBLK (SEGS * GRPS)           // 1776
#define SEG_F4 1024                  // float4 per segment

// ---------------------------------------------------------------------------
// Closed-form Jb[r][c] (256x256)
// ---------------------------------------------------------------------------
__device__ __forceinline__ float jb_val(int r, int c,
                                        const float* __restrict__ K,
                                        const float* __restrict__ C,
                                        const float* __restrict__ M) {
    if (r < HALF) {
        return (c == r + HALF) ? 1.0f : 0.0f;
    }
    int i = r - HALF;
    int j = (c < HALF) ? c : (c - HALF);
    int d = j - i;
    if (d < -1 || d > 1) return 0.0f;

    float Mi = M[i] * M_SCALE;
    if (c < HALF) {
        if (d == 0) {
            float v = -K[i] / Mi;
            if (i > 0) v -= K[i - 1] / Mi;
            return v;
        } else if (d == 1) {
            return K[i] / Mi;
        } else {
            return K[i - 1] / Mi;
        }
    } else {
        if (d == 0) {
            float v = -(C[i] * C_SCALE) / Mi;
            if (i > 0) v -= (C[i - 1] * C_SCALE) / Mi;
            return v;
        } else if (d == 1) {
            return (C[i] * C_SCALE) / Mi;
        } else {
            return (C[i - 1] * C_SCALE) / Mi;
        }
    }
}

// ---------------------------------------------------------------------------
// ONE fused kernel: 1776 blocks x 256 threads (exactly 2 waves at 6/SM).
// ---------------------------------------------------------------------------
__global__ void __launch_bounds__(SIZE, 6)
fused_kernel(const float* __restrict__ t,
             const float* __restrict__ y,
             const float* __restrict__ K,
             const float* __restrict__ C,
             const float* __restrict__ M,
             float* __restrict__ out) {
    __shared__ float sm[SIZE];   // [u(128) | v(128)]
    int bid = blockIdx.x;
    int tid = threadIdx.x;

    // ---- Part A: ydot rows, strided over the grid (1-2 rows per block) ----
    for (int row = bid; row < NROWS; row += NBLK) {
        sm[tid] = y[row * SIZE + tid];
        __syncthreads();

        float res;
        if (tid < HALF) {
            res = sm[HALF + tid];                 // ydot[:half] = v
        } else {
            int i = tid - HALF;
            float Mi = M[i] * M_SCALE;
            float acc = 0.0f;
            if (i < HALF - 1) {
                float f = K[i] * (sm[i + 1] - sm[i])
                        + (C[i] * C_SCALE) * (sm[HALF + i + 1] - sm[HALF + i]);
                acc += f / Mi;
            }
            if (i > 0) {
                float fm = K[i - 1] * (sm[i] - sm[i - 1])
                         + (C[i - 1] * C_SCALE) * (sm[HALF + i] - sm[HALF + i - 1]);
                acc -= fm / Mi;
            }
            if (i == HALF - 1) {
                acc -= (K[HALF - 1] * sm[HALF - 1]
                      + (C[HALF - 1] * C_SCALE) * sm[SIZE - 1]) / Mi;
            }
            if (i == 0) {
                acc += sinf(t[row]) / Mi;
            }
            res = acc;
        }
        out[row * SIZE + tid] = res;
        __syncthreads();   // protect sm before next iteration's load
    }

    // ---- Part B: compute this thread's 4 float4 of its Jb segment ---------
    int s = bid & (SEGS - 1);        // segment 0..15
    int g = bid >> 4;                // group   0..110
    int segBase = s * SEG_F4;        // float4 index within one Jb copy

    float4 jr[4];
    #pragma unroll
    for (int q = 0; q < 4; q++) {
        int e = (segBase + q * 256 + tid) * 4; // linear float index in Jb
        int r = e >> 8;
        int c = e & (SIZE - 1);
        jr[q].x = jb_val(r, c + 0, K, C, M);
        jr[q].y = jb_val(r, c + 1, K, C, M);
        jr[q].z = jb_val(r, c + 2, K, C, M);
        jr[q].w = jb_val(r, c + 3, K, C, M);
    }

    // ---- Part B: broadcast J (register replay, coalesced STG.128) ---------
    // Per copy: 4 independent STG.128, 16KB contiguous region (same pattern
    // that measured best in R2).
    float4* __restrict__ j4 = reinterpret_cast<float4*>(out + YDOT_FLOATS);
    #pragma unroll 4
    for (int k = g; k < NROWS; k += GRPS) {
        float4* dst = j4 + (long long)k * 16384 + segBase + tid;
        dst[0 * 256] = jr[0];
        dst[1 * 256] = jr[1];
        dst[2 * 256] = jr[2];
        dst[3 * 256] = jr[3];
    }
}

// ---------------------------------------------------------------------------
extern "C" void kernel_launch(void* const* d_in, const int* in_sizes, int n_in,
                              void* d_out, int out_size) {
    const float* t = (const float*)d_in[0];
    const float* y = (const float*)d_in[1];
    const float* K = (const float*)d_in[2];
    const float* C = (const float*)d_in[3];
    const float* M = (const float*)d_in[4];
    float* out = (float*)d_out;

    fused_kernel<<<NBLK, SIZE>>>(t, y, K, C, M, out);
}

// round 5
// speedup vs baseline: 1.0236x; 1.0051x over previous
#include <cuda_runtime.h>
#include <math.h>

// Problem constants
#define NCHUNK 32
#define NBATCH 64
#define HALF   128
#define SIZE   (2 * HALF)            // 256
#define NROWS  (NCHUNK * NBATCH)     // 2048
#define C_SCALE 1e-4f
#define M_SCALE 1e-5f

#define YDOT_FLOATS (NROWS * SIZE)   // 524288

// J broadcast: 16 segments x 111 groups = 1776 blocks = EXACTLY 2.0 waves
// at 6 blocks/SM (regs ~42) x 148 SMs.
// Each block holds one 16KB segment (4 float4/thread in registers) and writes
// it to a CONTIGUOUS range of batch copies (R2's winning store pattern):
// successive copies are 64KB apart, so each block's store stream stays inside
// a ~1.2MB window (1-2 TLB pages), unlike the strided variants (R3/R4) that
// cycled ~18 pages and lost ~8%.
#define SEGS 16
#define GRPS 111
#define NBLK (SEGS * GRPS)           // 1776
#define SEG_F4 1024                  // float4 per segment

// ---------------------------------------------------------------------------
// Closed-form Jb[r][c] (256x256)
// ---------------------------------------------------------------------------
__device__ __forceinline__ float jb_val(int r, int c,
                                        const float* __restrict__ K,
                                        const float* __restrict__ C,
                                        const float* __restrict__ M) {
    if (r < HALF) {
        return (c == r + HALF) ? 1.0f : 0.0f;
    }
    int i = r - HALF;
    int j = (c < HALF) ? c : (c - HALF);
    int d = j - i;
    if (d < -1 || d > 1) return 0.0f;

    float Mi = M[i] * M_SCALE;
    if (c < HALF) {
        if (d == 0) {
            float v = -K[i] / Mi;
            if (i > 0) v -= K[i - 1] / Mi;
            return v;
        } else if (d == 1) {
            return K[i] / Mi;
        } else {
            return K[i - 1] / Mi;
        }
    } else {
        if (d == 0) {
            float v = -(C[i] * C_SCALE) / Mi;
            if (i > 0) v -= (C[i - 1] * C_SCALE) / Mi;
            return v;
        } else if (d == 1) {
            return (C[i] * C_SCALE) / Mi;
        } else {
            return (C[i - 1] * C_SCALE) / Mi;
        }
    }
}

// ---------------------------------------------------------------------------
// ONE fused kernel: 1776 blocks x 256 threads (exactly 2 waves at 6/SM).
// ---------------------------------------------------------------------------
__global__ void __launch_bounds__(SIZE, 6)
fused_kernel(const float* __restrict__ t,
             const float* __restrict__ y,
             const float* __restrict__ K,
             const float* __restrict__ C,
             const float* __restrict__ M,
             float* __restrict__ out) {
    __shared__ float sm[SIZE];   // [u(128) | v(128)]
    int bid = blockIdx.x;
    int tid = threadIdx.x;

    // ---- Part A: ydot rows, strided over the grid (1-2 rows per block) ----
    for (int row = bid; row < NROWS; row += NBLK) {
        sm[tid] = y[row * SIZE + tid];
        __syncthreads();

        float res;
        if (tid < HALF) {
            res = sm[HALF + tid];                 // ydot[:half] = v
        } else {
            int i = tid - HALF;
            float Mi = M[i] * M_SCALE;
            float acc = 0.0f;
            if (i < HALF - 1) {
                float f = K[i] * (sm[i + 1] - sm[i])
                        + (C[i] * C_SCALE) * (sm[HALF + i + 1] - sm[HALF + i]);
                acc += f / Mi;
            }
            if (i > 0) {
                float fm = K[i - 1] * (sm[i] - sm[i - 1])
                         + (C[i - 1] * C_SCALE) * (sm[HALF + i] - sm[HALF + i - 1]);
                acc -= fm / Mi;
            }
            if (i == HALF - 1) {
                acc -= (K[HALF - 1] * sm[HALF - 1]
                      + (C[HALF - 1] * C_SCALE) * sm[SIZE - 1]) / Mi;
            }
            if (i == 0) {
                acc += sinf(t[row]) / Mi;
            }
            res = acc;
        }
        out[row * SIZE + tid] = res;
        __syncthreads();   // protect sm before next iteration's load
    }

    // ---- Part B: compute this thread's 4 float4 of its Jb segment ---------
    int s = bid & (SEGS - 1);        // segment 0..15
    int g = bid >> 4;                // group   0..110
    int segBase = s * SEG_F4;        // float4 index within one Jb copy

    float4 jr[4];
    #pragma unroll
    for (int q = 0; q < 4; q++) {
        int e = (segBase + q * 256 + tid) * 4; // linear float index in Jb
        int r = e >> 8;
        int c = e & (SIZE - 1);
        jr[q].x = jb_val(r, c + 0, K, C, M);
        jr[q].y = jb_val(r, c + 1, K, C, M);
        jr[q].z = jb_val(r, c + 2, K, C, M);
        jr[q].w = jb_val(r, c + 3, K, C, M);
    }

    // ---- Part B: broadcast J over a CONTIGUOUS copy range -----------------
    // (4 independent STG.128 per copy; copies 64KB apart — R2's pattern)
    int k0 = (g * NROWS) / GRPS;
    int k1 = ((g + 1) * NROWS) / GRPS;

    float4* __restrict__ j4 = reinterpret_cast<float4*>(out + YDOT_FLOATS);
    #pragma unroll 4
    for (int k = k0; k < k1; k++) {
        float4* dst = j4 + (long long)k * 16384 + segBase + tid;
        dst[0 * 256] = jr[0];
        dst[1 * 256] = jr[1];
        dst[2 * 256] = jr[2];
        dst[3 * 256] = jr[3];
    }
}

// ---------------------------------------------------------------------------
extern "C" void kernel_launch(void* const* d_in, const int* in_sizes, int n_in,
                              void* d_out, int out_size) {
    const float* t = (const float*)d_in[0];
    const float* y = (const float*)d_in[1];
    const float* K = (const float*)d_in[2];
    const float* C = (const float*)d_in[3];
    const float* M = (const float*)d_in[4];
    float* out = (float*)d_out;

    fused_kernel<<<NBLK, SIZE>>>(t, y, K, C, M, out);
}